// round 5
// baseline (speedup 1.0000x reference)
#include <cuda_runtime.h>
#include <cuda_bf16.h>
#include <math.h>
#include <stdint.h>

// Problem dims
#define Bz   2
#define Sq   2048
#define Dm   1024
#define Hn   16
#define DH   64
#define DFF  4096
#define Mrows (Bz * Sq)      // 4096
#define BH   (Bz * Hn)       // 32

// ---------------- scratch ----------------------------------------------------
__device__ float g_xn[(size_t)Mrows * Dm];
__device__ float g_qkv[(size_t)Mrows * 3 * Dm];
__device__ float g_attnout[(size_t)Mrows * Dm];
__device__ float g_x2[(size_t)Mrows * Dm];
__device__ float g_h[(size_t)Mrows * DFF];

// ---------------- helpers ----------------------------------------------------
__device__ __forceinline__ uint32_t f2tf32(float f) {
    uint32_t u;
    asm("cvt.rna.tf32.f32 %0, %1;" : "=r"(u) : "f"(f));
    return u;
}

__device__ __forceinline__ void mma_tf32(float c[4],
    uint32_t a0, uint32_t a1, uint32_t a2, uint32_t a3,
    uint32_t b0, uint32_t b1)
{
    asm volatile(
        "mma.sync.aligned.m16n8k8.row.col.f32.tf32.tf32.f32 "
        "{%0,%1,%2,%3}, {%4,%5,%6,%7}, {%8,%9}, {%0,%1,%2,%3};\n"
        : "+f"(c[0]), "+f"(c[1]), "+f"(c[2]), "+f"(c[3])
        : "r"(a0), "r"(a1), "r"(a2), "r"(a3), "r"(b0), "r"(b1));
}

__device__ __forceinline__ void cp16(uint32_t smem_addr, const void* gptr) {
    asm volatile("cp.async.cg.shared.global [%0], [%1], 16;\n"
                 :: "r"(smem_addr), "l"(gptr));
}
#define CP_COMMIT asm volatile("cp.async.commit_group;\n" ::)
#define CP_WAIT(n) asm volatile("cp.async.wait_group %0;\n" :: "n"(n))

// ---------------- RMSNorm ----------------------------------------------------
__global__ __launch_bounds__(256)
void rmsnorm_kernel(const float* __restrict__ x, const float* __restrict__ scale,
                    float* __restrict__ out)
{
    int row = blockIdx.x;
    const float* xr = x + (size_t)row * Dm;
    float ss = 0.f;
    #pragma unroll
    for (int i = threadIdx.x; i < Dm; i += 256) { float v = xr[i]; ss += v * v; }
    __shared__ float red[256];
    red[threadIdx.x] = ss; __syncthreads();
    #pragma unroll
    for (int s = 128; s > 0; s >>= 1) {
        if (threadIdx.x < s) red[threadIdx.x] += red[threadIdx.x + s];
        __syncthreads();
    }
    float rms = rsqrtf(red[0] * (1.0f / Dm) + 1e-8f);
    float* orow = out + (size_t)row * Dm;
    #pragma unroll
    for (int i = threadIdx.x; i < Dm; i += 256)
        orow[i] = scale[i] * xr[i] * rms;
}

// ---------------- TF32 tensor-core GEMM with cp.async double buffering -------
// C = A[M,K] @ B[K,N].  EPI: 0 = +bias, 1 = +bias+residual, 2 = +bias, gelu
// Block tile 128x128, warp tile 64x32 (8 warps), K-chunk 32, 2-stage pipeline.
// Raw fp32 bits fed to tf32 mma (RZ truncation).
#define AS_STRIDE 36
#define BS_STRIDE 136
#define AS_ELEMS (128 * AS_STRIDE)
#define BS_ELEMS (32 * BS_STRIDE)
#define GEMM_SMEM ((2 * (AS_ELEMS + BS_ELEMS)) * 4)

template<int EPI>
__global__ __launch_bounds__(256, 2)
void gemm_tc(const float* __restrict__ A, const float* __restrict__ Bm,
             const float* __restrict__ bias, const float* __restrict__ resid,
             float* __restrict__ C, int M, int N, int K)
{
    extern __shared__ float smem[];
    float* Asm = smem;                       // [2][128][36]
    float* Bsm = smem + 2 * AS_ELEMS;        // [2][32][136]

    const int tid = threadIdx.x, warp = tid >> 5, lane = tid & 31;
    const int bm = blockIdx.y * 128, bn = blockIdx.x * 128;
    const int warpM = (warp & 1) * 64, warpN = (warp >> 1) * 32;
    const int r0 = lane >> 2, c0 = lane & 3;
    float c[4][4][4] = {};

    // Per-thread copy coordinates (each thread: 4 x 16B per operand)
    const int am  = tid >> 1;                 // A row 0..127 (2 threads/row)
    const int ac0 = (tid & 1) * 16;           // A col base (floats): 0 or 16
    const int bk  = tid >> 3;                 // B row 0..31 (8 threads/row)
    const int bc0 = (tid & 7) * 16;           // B col base (floats): 0..112

    const uint32_t sA = (uint32_t)__cvta_generic_to_shared(Asm);
    const uint32_t sB = (uint32_t)__cvta_generic_to_shared(Bsm);

    const int nk = K >> 5;

    auto load_tile = [&](int i, int buf) {
        const int k0 = i << 5;
        // A: 128 rows x 32 k
        const float* ga = &A[(size_t)(bm + am) * K + k0 + ac0];
        uint32_t da = sA + (uint32_t)(buf * AS_ELEMS + am * AS_STRIDE + ac0) * 4;
        #pragma unroll
        for (int j = 0; j < 4; j++)
            cp16(da + j * 16, ga + j * 4);
        // B: 32 rows x 128 n
        const float* gb = &Bm[(size_t)(k0 + bk) * N + bn + bc0];
        uint32_t db = sB + (uint32_t)(buf * BS_ELEMS + bk * BS_STRIDE + bc0) * 4;
        #pragma unroll
        for (int j = 0; j < 4; j++)
            cp16(db + j * 16, gb + j * 4);
    };

    load_tile(0, 0);
    CP_COMMIT;

    for (int i = 0; i < nk; i++) {
        const int buf = i & 1;
        if (i + 1 < nk) {
            load_tile(i + 1, buf ^ 1);
            CP_COMMIT;
            CP_WAIT(1);
        } else {
            CP_WAIT(0);
        }
        __syncthreads();

        const float* Ab = Asm + buf * AS_ELEMS;
        const float* Bb = Bsm + buf * BS_ELEMS;
        #pragma unroll
        for (int kk = 0; kk < 32; kk += 8) {
            uint32_t a[4][4], b[4][2];
            #pragma unroll
            for (int mt = 0; mt < 4; mt++) {
                int m = warpM + mt * 16;
                a[mt][0] = __float_as_uint(Ab[(m + r0) * AS_STRIDE + kk + c0]);
                a[mt][1] = __float_as_uint(Ab[(m + r0 + 8) * AS_STRIDE + kk + c0]);
                a[mt][2] = __float_as_uint(Ab[(m + r0) * AS_STRIDE + kk + c0 + 4]);
                a[mt][3] = __float_as_uint(Ab[(m + r0 + 8) * AS_STRIDE + kk + c0 + 4]);
            }
            #pragma unroll
            for (int nt = 0; nt < 4; nt++) {
                int n = warpN + nt * 8 + r0;
                b[nt][0] = __float_as_uint(Bb[(kk + c0) * BS_STRIDE + n]);
                b[nt][1] = __float_as_uint(Bb[(kk + c0 + 4) * BS_STRIDE + n]);
            }
            #pragma unroll
            for (int mt = 0; mt < 4; mt++)
                #pragma unroll
                for (int nt = 0; nt < 4; nt++)
                    mma_tf32(c[mt][nt], a[mt][0], a[mt][1], a[mt][2], a[mt][3],
                             b[nt][0], b[nt][1]);
        }
        __syncthreads();
    }

    #pragma unroll
    for (int mt = 0; mt < 4; mt++) {
        #pragma unroll
        for (int nt = 0; nt < 4; nt++) {
            #pragma unroll
            for (int ci = 0; ci < 4; ci++) {
                int row = bm + warpM + mt * 16 + r0 + ((ci >= 2) ? 8 : 0);
                int col = bn + warpN + nt * 8 + c0 * 2 + (ci & 1);
                float v = c[mt][nt][ci] + bias[col];
                if (EPI == 1) v += resid[(size_t)row * N + col];
                if (EPI == 2) v = 0.5f * v * (1.0f + erff(v * 0.70710678118654752f));
                C[(size_t)row * N + col] = v;
            }
        }
    }
}

// ---------------- fused flash attention --------------------------------------
#define QS_STRIDE 68
#define KS_STRIDE 68
#define VS_STRIDE 72
#define PS_STRIDE 68
#define FLASH_SMEM ((128 * QS_STRIDE + 64 * KS_STRIDE + 64 * VS_STRIDE + 128 * PS_STRIDE) * 4)

__global__ __launch_bounds__(256, 2)
void flash_attn(const float* __restrict__ qkv, float* __restrict__ attnout)
{
    extern __shared__ uint32_t sm[];
    uint32_t* Qs = sm;
    uint32_t* Ks = Qs + 128 * QS_STRIDE;
    uint32_t* Vs = Ks + 64 * KS_STRIDE;
    uint32_t* Ps = Vs + 64 * VS_STRIDE;

    const int bh = blockIdx.y, b = bh >> 4, h = bh & 15;
    const int q0 = blockIdx.x * 128;
    const int tid = threadIdx.x, warp = tid >> 5, lane = tid & 31;
    const int r0 = lane >> 2, c0 = lane & 3;
    const int qrow = warp * 16;
    const float slope = exp2f(-0.5f * (float)(h + 1));
    const size_t base = (size_t)b * Sq * (3 * Dm) + (size_t)h * DH;

    #pragma unroll
    for (int p = 0; p < 8; p++) {
        int idx = tid + p * 256;
        int r = idx >> 4, d4 = idx & 15;
        float4 v = *(const float4*)&qkv[base + (size_t)(q0 + r) * (3 * Dm) + d4 * 4];
        uint32_t* dst = &Qs[r * QS_STRIDE + d4 * 4];
        dst[0] = f2tf32(v.x); dst[1] = f2tf32(v.y);
        dst[2] = f2tf32(v.z); dst[3] = f2tf32(v.w);
    }

    float m_i[2] = {-1e30f, -1e30f};
    float l_i[2] = {0.f, 0.f};
    float o[8][4] = {};

    for (int t0 = 0; t0 < Sq; t0 += 64) {
        __syncthreads();
        #pragma unroll
        for (int p = 0; p < 4; p++) {
            int idx = tid + p * 256;
            int r = idx >> 4, d4 = idx & 15;
            const float* src = &qkv[base + (size_t)(t0 + r) * (3 * Dm) + d4 * 4];
            float4 vk = *(const float4*)(src + Dm);
            float4 vv = *(const float4*)(src + 2 * Dm);
            uint32_t* dk = &Ks[r * KS_STRIDE + d4 * 4];
            dk[0] = f2tf32(vk.x); dk[1] = f2tf32(vk.y);
            dk[2] = f2tf32(vk.z); dk[3] = f2tf32(vk.w);
            uint32_t* dv = &Vs[r * VS_STRIDE + d4 * 4];
            dv[0] = f2tf32(vv.x); dv[1] = f2tf32(vv.y);
            dv[2] = f2tf32(vv.z); dv[3] = f2tf32(vv.w);
        }
        __syncthreads();

        float s[8][4] = {};
        #pragma unroll
        for (int kk = 0; kk < 64; kk += 8) {
            uint32_t a0 = Qs[(qrow + r0) * QS_STRIDE + kk + c0];
            uint32_t a1 = Qs[(qrow + r0 + 8) * QS_STRIDE + kk + c0];
            uint32_t a2 = Qs[(qrow + r0) * QS_STRIDE + kk + c0 + 4];
            uint32_t a3 = Qs[(qrow + r0 + 8) * QS_STRIDE + kk + c0 + 4];
            #pragma unroll
            for (int nt = 0; nt < 8; nt++) {
                uint32_t b0 = Ks[(nt * 8 + r0) * KS_STRIDE + kk + c0];
                uint32_t b1 = Ks[(nt * 8 + r0) * KS_STRIDE + kk + c0 + 4];
                mma_tf32(s[nt], a0, a1, a2, a3, b0, b1);
            }
        }

        const int si0 = q0 + qrow + r0, si1 = si0 + 8;
        float mx0 = -1e30f, mx1 = -1e30f;
        #pragma unroll
        for (int nt = 0; nt < 8; nt++) {
            int tj = t0 + nt * 8 + c0 * 2;
            s[nt][0] = s[nt][0] * 0.125f - slope * fabsf((float)(si0 - tj));
            s[nt][1] = s[nt][1] * 0.125f - slope * fabsf((float)(si0 - tj - 1));
            s[nt][2] = s[nt][2] * 0.125f - slope * fabsf((float)(si1 - tj));
            s[nt][3] = s[nt][3] * 0.125f - slope * fabsf((float)(si1 - tj - 1));
            mx0 = fmaxf(mx0, fmaxf(s[nt][0], s[nt][1]));
            mx1 = fmaxf(mx1, fmaxf(s[nt][2], s[nt][3]));
        }
        mx0 = fmaxf(mx0, __shfl_xor_sync(0xffffffffu, mx0, 1));
        mx0 = fmaxf(mx0, __shfl_xor_sync(0xffffffffu, mx0, 2));
        mx1 = fmaxf(mx1, __shfl_xor_sync(0xffffffffu, mx1, 1));
        mx1 = fmaxf(mx1, __shfl_xor_sync(0xffffffffu, mx1, 2));

        float mn0 = fmaxf(m_i[0], mx0), mn1 = fmaxf(m_i[1], mx1);
        float corr0 = __expf(m_i[0] - mn0), corr1 = __expf(m_i[1] - mn1);
        m_i[0] = mn0; m_i[1] = mn1;

        float sum0 = 0.f, sum1 = 0.f;
        #pragma unroll
        for (int nt = 0; nt < 8; nt++) {
            s[nt][0] = __expf(s[nt][0] - mn0);
            s[nt][1] = __expf(s[nt][1] - mn0);
            s[nt][2] = __expf(s[nt][2] - mn1);
            s[nt][3] = __expf(s[nt][3] - mn1);
            sum0 += s[nt][0] + s[nt][1];
            sum1 += s[nt][2] + s[nt][3];
            uint32_t* d0 = &Ps[(qrow + r0) * PS_STRIDE + nt * 8 + c0 * 2];
            d0[0] = f2tf32(s[nt][0]); d0[1] = f2tf32(s[nt][1]);
            uint32_t* d1 = &Ps[(qrow + r0 + 8) * PS_STRIDE + nt * 8 + c0 * 2];
            d1[0] = f2tf32(s[nt][2]); d1[1] = f2tf32(s[nt][3]);
        }
        sum0 += __shfl_xor_sync(0xffffffffu, sum0, 1);
        sum0 += __shfl_xor_sync(0xffffffffu, sum0, 2);
        sum1 += __shfl_xor_sync(0xffffffffu, sum1, 1);
        sum1 += __shfl_xor_sync(0xffffffffu, sum1, 2);
        l_i[0] = l_i[0] * corr0 + sum0;
        l_i[1] = l_i[1] * corr1 + sum1;
        #pragma unroll
        for (int nt = 0; nt < 8; nt++) {
            o[nt][0] *= corr0; o[nt][1] *= corr0;
            o[nt][2] *= corr1; o[nt][3] *= corr1;
        }
        __syncwarp();

        #pragma unroll
        for (int kk = 0; kk < 64; kk += 8) {
            uint32_t a0 = Ps[(qrow + r0) * PS_STRIDE + kk + c0];
            uint32_t a1 = Ps[(qrow + r0 + 8) * PS_STRIDE + kk + c0];
            uint32_t a2 = Ps[(qrow + r0) * PS_STRIDE + kk + c0 + 4];
            uint32_t a3 = Ps[(qrow + r0 + 8) * PS_STRIDE + kk + c0 + 4];
            #pragma unroll
            for (int nt = 0; nt < 8; nt++) {
                uint32_t b0 = Vs[(kk + c0) * VS_STRIDE + nt * 8 + r0];
                uint32_t b1 = Vs[(kk + c0 + 4) * VS_STRIDE + nt * 8 + r0];
                mma_tf32(o[nt], a0, a1, a2, a3, b0, b1);
            }
        }
    }

    float inv0 = 1.f / l_i[0], inv1 = 1.f / l_i[1];
    size_t obase = ((size_t)b * Sq + q0 + qrow) * Dm + (size_t)h * DH;
    #pragma unroll
    for (int nt = 0; nt < 8; nt++) {
        int d = nt * 8 + c0 * 2;
        attnout[obase + (size_t)r0 * Dm + d]           = o[nt][0] * inv0;
        attnout[obase + (size_t)r0 * Dm + d + 1]       = o[nt][1] * inv0;
        attnout[obase + (size_t)(r0 + 8) * Dm + d]     = o[nt][2] * inv1;
        attnout[obase + (size_t)(r0 + 8) * Dm + d + 1] = o[nt][3] * inv1;
    }
}

// ---------------- host driver ------------------------------------------------
extern "C" void kernel_launch(void* const* d_in, const int* in_sizes, int n_in,
                              void* d_out, int out_size)
{
    const float* x      = (const float*)d_in[0];
    const float* scale1 = (const float*)d_in[1];
    const float* scale2 = (const float*)d_in[2];
    const float* w_qkv  = (const float*)d_in[3];
    const float* b_qkv  = (const float*)d_in[4];
    const float* w_out  = (const float*)d_in[5];
    const float* b_out  = (const float*)d_in[6];
    const float* w1     = (const float*)d_in[7];
    const float* b1     = (const float*)d_in[8];
    const float* w2     = (const float*)d_in[9];
    const float* b2     = (const float*)d_in[10];
    float* out = (float*)d_out;

    void *p_xn, *p_qkv, *p_attnout, *p_x2, *p_h;
    cudaGetSymbolAddress(&p_xn, g_xn);
    cudaGetSymbolAddress(&p_qkv, g_qkv);
    cudaGetSymbolAddress(&p_attnout, g_attnout);
    cudaGetSymbolAddress(&p_x2, g_x2);
    cudaGetSymbolAddress(&p_h, g_h);
    float* xn      = (float*)p_xn;
    float* qkv     = (float*)p_qkv;
    float* attnout = (float*)p_attnout;
    float* x2      = (float*)p_x2;
    float* hbuf    = (float*)p_h;

    cudaFuncSetAttribute(flash_attn, cudaFuncAttributeMaxDynamicSharedMemorySize,
                         FLASH_SMEM);
    cudaFuncSetAttribute(gemm_tc<0>, cudaFuncAttributeMaxDynamicSharedMemorySize,
                         GEMM_SMEM);
    cudaFuncSetAttribute(gemm_tc<1>, cudaFuncAttributeMaxDynamicSharedMemorySize,
                         GEMM_SMEM);
    cudaFuncSetAttribute(gemm_tc<2>, cudaFuncAttributeMaxDynamicSharedMemorySize,
                         GEMM_SMEM);

    // 1) RMSNorm 1
    rmsnorm_kernel<<<Mrows, 256>>>(x, scale1, xn);

    // 2) QKV projection
    gemm_tc<0><<<dim3(3 * Dm / 128, Mrows / 128), 256, GEMM_SMEM>>>(
        xn, w_qkv, b_qkv, nullptr, qkv, Mrows, 3 * Dm, Dm);

    // 3-5) fused attention
    flash_attn<<<dim3(Sq / 128, BH), 256, FLASH_SMEM>>>(qkv, attnout);

    // 6) out projection + residual
    gemm_tc<1><<<dim3(Dm / 128, Mrows / 128), 256, GEMM_SMEM>>>(
        attnout, w_out, b_out, x, x2, Mrows, Dm, Dm);

    // 7) RMSNorm 2
    rmsnorm_kernel<<<Mrows, 256>>>(x2, scale2, xn);

    // 8) FFN up + GELU
    gemm_tc<2><<<dim3(DFF / 128, Mrows / 128), 256, GEMM_SMEM>>>(
        xn, w1, b1, nullptr, hbuf, Mrows, DFF, Dm);

    // 9) FFN down + residual
    gemm_tc<1><<<dim3(Dm / 128, Mrows / 128), 256, GEMM_SMEM>>>(
        hbuf, w2, b2, x2, out, Mrows, Dm, DFF);
}